// round 1
// baseline (speedup 1.0000x reference)
#include <cuda_runtime.h>

#define D_MODEL 1024
#define NHEAD   16
#define DHEAD   64
#define BATCH   4
#define SEQ     2048
#define ROWS    (BATCH * SEQ)          // 8192
#define QKV_N   (3 * D_MODEL)          // 3072

// Scratch (allocation-free rule: __device__ globals)
__device__ float g_Q[BATCH * NHEAD * SEQ * DHEAD];   // [B,H,L,Dh]
__device__ float g_K[BATCH * NHEAD * SEQ * DHEAD];
__device__ float g_V[BATCH * NHEAD * SEQ * DHEAD];
__device__ float g_ctx[ROWS * D_MODEL];              // [B,L,H*Dh]

// ---------------------------------------------------------------------------
// GEMM tile config: 128x64 block tile, K-slab 16, 256 threads, 8x4 per thread
// ---------------------------------------------------------------------------
#define BM 128
#define BN 64
#define BK 16

// QKV projection: C[8192,3072] = X[8192,1024] @ W[1024,3072] + bias,
// scattered into g_Q/g_K/g_V with per-head layout [B,H,L,Dh].
__global__ __launch_bounds__(256) void qkv_gemm_kernel(
    const float* __restrict__ X, const float* __restrict__ W,
    const float* __restrict__ bias)
{
    __shared__ float As[BK][BM];
    __shared__ float Bs[BK][BN];

    const int tid = threadIdx.x;
    const int bn  = blockIdx.x * BN;
    const int bm  = blockIdx.y * BM;
    const int tx  = tid & 15;          // col group (x4)
    const int ty  = tid >> 4;          // row group (x8)
    const int aRow = tid >> 2, aCol = (tid & 3) << 2;
    const int bRow = tid >> 4, bCol = (tid & 15) << 2;

    float acc[8][4];
    #pragma unroll
    for (int i = 0; i < 8; i++)
        #pragma unroll
        for (int j = 0; j < 4; j++) acc[i][j] = 0.f;

    for (int k0 = 0; k0 < D_MODEL; k0 += BK) {
        #pragma unroll
        for (int h = 0; h < 2; h++) {
            int r = aRow + h * 64;
            float4 a = *(const float4*)&X[(bm + r) * D_MODEL + k0 + aCol];
            As[aCol + 0][r] = a.x;
            As[aCol + 1][r] = a.y;
            As[aCol + 2][r] = a.z;
            As[aCol + 3][r] = a.w;
        }
        *(float4*)&Bs[bRow][bCol] =
            *(const float4*)&W[(k0 + bRow) * QKV_N + bn + bCol];
        __syncthreads();

        #pragma unroll
        for (int k = 0; k < BK; k++) {
            float a[8], b[4];
            #pragma unroll
            for (int i = 0; i < 8; i++) a[i] = As[k][ty * 8 + i];
            #pragma unroll
            for (int j = 0; j < 4; j++) b[j] = Bs[k][tx * 4 + j];
            #pragma unroll
            for (int i = 0; i < 8; i++)
                #pragma unroll
                for (int j = 0; j < 4; j++) acc[i][j] += a[i] * b[j];
        }
        __syncthreads();
    }

    // Whole block lives inside one (s, head) column slab since bn % 64 == 0.
    #pragma unroll
    for (int i = 0; i < 8; i++) {
        int m  = bm + ty * 8 + i;
        int bb = m >> 11;          // / SEQ
        int ll = m & (SEQ - 1);
        #pragma unroll
        for (int j = 0; j < 4; j++) {
            int n = bn + tx * 4 + j;
            float v = acc[i][j] + bias[n];
            int s  = n >> 10;      // 0=Q 1=K 2=V
            int r  = n & 1023;
            int hh = r >> 6;
            int dd = r & 63;
            float* dst = (s == 0) ? g_Q : (s == 1) ? g_K : g_V;
            dst[(((bb * NHEAD) + hh) * SEQ + ll) * DHEAD + dd] = v;
        }
    }
}

// Output projection: out[8192,1024] = ctx[8192,1024] @ Wout[1024,1024] + bias
__global__ __launch_bounds__(256) void out_gemm_kernel(
    const float* __restrict__ W, const float* __restrict__ bias,
    float* __restrict__ out)
{
    __shared__ float As[BK][BM];
    __shared__ float Bs[BK][BN];

    const int tid = threadIdx.x;
    const int bn  = blockIdx.x * BN;
    const int bm  = blockIdx.y * BM;
    const int tx  = tid & 15;
    const int ty  = tid >> 4;
    const int aRow = tid >> 2, aCol = (tid & 3) << 2;
    const int bRow = tid >> 4, bCol = (tid & 15) << 2;

    float acc[8][4];
    #pragma unroll
    for (int i = 0; i < 8; i++)
        #pragma unroll
        for (int j = 0; j < 4; j++) acc[i][j] = 0.f;

    for (int k0 = 0; k0 < D_MODEL; k0 += BK) {
        #pragma unroll
        for (int h = 0; h < 2; h++) {
            int r = aRow + h * 64;
            float4 a = *(const float4*)&g_ctx[(bm + r) * D_MODEL + k0 + aCol];
            As[aCol + 0][r] = a.x;
            As[aCol + 1][r] = a.y;
            As[aCol + 2][r] = a.z;
            As[aCol + 3][r] = a.w;
        }
        *(float4*)&Bs[bRow][bCol] =
            *(const float4*)&W[(k0 + bRow) * D_MODEL + bn + bCol];
        __syncthreads();

        #pragma unroll
        for (int k = 0; k < BK; k++) {
            float a[8], b[4];
            #pragma unroll
            for (int i = 0; i < 8; i++) a[i] = As[k][ty * 8 + i];
            #pragma unroll
            for (int j = 0; j < 4; j++) b[j] = Bs[k][tx * 4 + j];
            #pragma unroll
            for (int i = 0; i < 8; i++)
                #pragma unroll
                for (int j = 0; j < 4; j++) acc[i][j] += a[i] * b[j];
        }
        __syncthreads();
    }

    #pragma unroll
    for (int i = 0; i < 8; i++) {
        int m = bm + ty * 8 + i;
        #pragma unroll
        for (int j = 0; j < 4; j++) {
            int n = bn + tx * 4 + j;
            out[m * D_MODEL + n] = acc[i][j] + bias[n];
        }
    }
}

// ---------------------------------------------------------------------------
// Flash attention, fp32. 1 thread = 1 query row; q + O accumulator in regs.
// Block: 128 threads = 128 query rows. K/V staged in smem in tiles of 32 keys.
// Score tile staged through padded smem to keep s[] out of local memory.
// grid = (SEQ/128, NHEAD, BATCH)
// ---------------------------------------------------------------------------
#define KT 32   // keys per tile

__global__ __launch_bounds__(128) void attn_kernel()
{
    __shared__ float Ks[KT * DHEAD];       // 8 KB
    __shared__ float Vs[KT * DHEAD];       // 8 KB
    __shared__ float Ss[128][KT + 1];      // padded: conflict-free row access

    const int tid = threadIdx.x;
    const int b  = blockIdx.z;
    const int h  = blockIdx.y;
    const int q0 = blockIdx.x * 128;

    const int head_off = ((b * NHEAD) + h) * SEQ * DHEAD;
    const float* __restrict__ Qb = g_Q + head_off;
    const float* __restrict__ Kb = g_K + head_off;
    const float* __restrict__ Vb = g_V + head_off;

    // Load this thread's query row into registers
    float q[DHEAD];
    {
        const float4* qr = (const float4*)(Qb + (q0 + tid) * DHEAD);
        #pragma unroll
        for (int i = 0; i < DHEAD / 4; i++) {
            float4 t = qr[i];
            q[4*i+0] = t.x; q[4*i+1] = t.y; q[4*i+2] = t.z; q[4*i+3] = t.w;
        }
    }

    float O[DHEAD];
    #pragma unroll
    for (int d = 0; d < DHEAD; d++) O[d] = 0.f;
    float m = -1e30f, l = 0.f;

    for (int kt = 0; kt < SEQ / KT; kt++) {
        // Stage K/V tiles (contiguous in per-head layout -> coalesced)
        const float4* ksrc = (const float4*)(Kb + kt * KT * DHEAD);
        const float4* vsrc = (const float4*)(Vb + kt * KT * DHEAD);
        #pragma unroll
        for (int i = 0; i < (KT * DHEAD / 4) / 128; i++) {
            ((float4*)Ks)[tid + i * 128] = ksrc[tid + i * 128];
            ((float4*)Vs)[tid + i * 128] = vsrc[tid + i * 128];
        }
        __syncthreads();

        // Pass 1: scores for this thread's row (smem K reads broadcast)
        for (int j = 0; j < KT; j++) {
            float a0 = 0.f, a1 = 0.f, a2 = 0.f, a3 = 0.f;
            #pragma unroll
            for (int d = 0; d < DHEAD; d += 4) {
                a0 += q[d + 0] * Ks[j * DHEAD + d + 0];
                a1 += q[d + 1] * Ks[j * DHEAD + d + 1];
                a2 += q[d + 2] * Ks[j * DHEAD + d + 2];
                a3 += q[d + 3] * Ks[j * DHEAD + d + 3];
            }
            Ss[tid][j] = (a0 + a1 + a2 + a3) * 0.125f;   // 1/sqrt(64)
        }

        // Tile max + online rescale
        float mt = m;
        for (int j = 0; j < KT; j++) mt = fmaxf(mt, Ss[tid][j]);
        float alpha = __expf(m - mt);
        m = mt;
        l *= alpha;
        #pragma unroll
        for (int d = 0; d < DHEAD; d++) O[d] *= alpha;

        // Pass 2: accumulate P @ V
        for (int j = 0; j < KT; j++) {
            float p = __expf(Ss[tid][j] - m);
            l += p;
            #pragma unroll
            for (int d = 0; d < DHEAD; d++)
                O[d] += p * Vs[j * DHEAD + d];
        }
        __syncthreads();
    }

    // Write context in [B, L, H*Dh] layout
    float inv = 1.f / l;
    float* dst = g_ctx + (b * SEQ + q0 + tid) * D_MODEL + h * DHEAD;
    #pragma unroll
    for (int i = 0; i < DHEAD / 4; i++) {
        float4 t;
        t.x = O[4*i+0] * inv; t.y = O[4*i+1] * inv;
        t.z = O[4*i+2] * inv; t.w = O[4*i+3] * inv;
        ((float4*)dst)[i] = t;
    }
}

// ---------------------------------------------------------------------------

extern "C" void kernel_launch(void* const* d_in, const int* in_sizes, int n_in,
                              void* d_out, int out_size)
{
    const float* x     = (const float*)d_in[0];
    const float* w_qkv = (const float*)d_in[1];
    const float* b_qkv = (const float*)d_in[2];
    const float* w_out = (const float*)d_in[3];
    const float* b_out = (const float*)d_in[4];
    float* out = (float*)d_out;

    (void)in_sizes; (void)n_in; (void)out_size;

    // 1) QKV projection + scatter into per-head layout
    qkv_gemm_kernel<<<dim3(QKV_N / BN, ROWS / BM), 256>>>(x, w_qkv, b_qkv);

    // 2) Attention
    attn_kernel<<<dim3(SEQ / 128, NHEAD, BATCH), 128>>>();

    // 3) Output projection
    out_gemm_kernel<<<dim3(D_MODEL / BN, ROWS / BM), 256>>>(w_out, b_out, out);
}

// round 7
// speedup vs baseline: 1.0129x; 1.0129x over previous
#include <cuda_runtime.h>
#include <cstdint>

#define D_MODEL 1024
#define NHEAD   16
#define DHEAD   64
#define BATCH   4
#define SEQ     2048
#define ROWS    (BATCH * SEQ)          // 8192
#define QKV_N   (3 * D_MODEL)          // 3072
#define KDIM    1024

// Scratch (allocation-free rule: __device__ globals)
__device__ float g_Q[BATCH * NHEAD * SEQ * DHEAD];   // [B,H,L,Dh]
__device__ float g_K[BATCH * NHEAD * SEQ * DHEAD];
__device__ float g_V[BATCH * NHEAD * SEQ * DHEAD];
__device__ float g_ctx[ROWS * D_MODEL];              // [B,L,H*Dh]

// ---------------------------------------------------------------------------
// helpers
// ---------------------------------------------------------------------------
__device__ __forceinline__ float f2tf32(float x) {
    uint32_t b;
    asm("cvt.rna.tf32.f32 %0, %1;" : "=r"(b) : "f"(x));
    return __uint_as_float(b);
}

// D += A*B, m16n8k8 tf32 (legacy tensor-core path, portable PTX)
__device__ __forceinline__ void mma_tf32(float* d, const uint32_t* a, const uint32_t* b) {
    asm volatile(
        "mma.sync.aligned.m16n8k8.row.col.f32.tf32.tf32.f32 "
        "{%0,%1,%2,%3}, {%4,%5,%6,%7}, {%8,%9}, {%0,%1,%2,%3};"
        : "+f"(d[0]), "+f"(d[1]), "+f"(d[2]), "+f"(d[3])
        : "r"(a[0]), "r"(a[1]), "r"(a[2]), "r"(a[3]), "r"(b[0]), "r"(b[1]));
}

// ---------------------------------------------------------------------------
// mma.sync tf32 GEMM: C[M,N] = A[M,1024] @ W[1024,N] + bias
// CTA tile 128x128, BK=32, 256 threads = 8 warps (2 m x 4 n), warp tile 64x32.
// smem holds fragment-permuted tf32 so mainloop frag loads are LDS.128/LDS.64.
//
// Fragment layouts (PTX m16n8k8.row.col, g = lane>>2, t4 = lane&3):
//   A regs a0..a3 -> (row,k) = (g,t4), (g+8,t4), (g,t4+4), (g+8,t4+4)
//   B regs b0,b1  -> (k,n)   = (t4,g), (t4+4,g)
//   D regs d0..d3 -> (row,n) = (g,2t4), (g,2t4+1), (g+8,2t4), (g+8,2t4+1)
// A tile (16m x 8k) stored as float[128]: idx = lane*4 + e, lane = g*4+e4,
//   e = (mr>>3) + 2*(kk>>2), where element e4 = kk&3 of the source float4.
// B tile (8k x 8n) stored as float[64]: idx = lane*2 + regb, lane = nn*4+(kk&3).
// ---------------------------------------------------------------------------
#define GBM 128
#define GBN 128
#define GBK 32
#define NKIT (KDIM / GBK)        // 32
#define ABUF 4096                // floats per A buffer (128*32)
#define BBUF 4096                // floats per B buffer (32*128)

template<int QKV>
__global__ __launch_bounds__(256, 2) void tc_gemm(
    const float* __restrict__ Ain, const float* __restrict__ W,
    const float* __restrict__ bias, float* __restrict__ out, int ldn)
{
    extern __shared__ float sm[];
    float* As = sm;                 // 2 * 4096
    float* Bs = sm + 2 * ABUF;      // 2 * 4096

    const int tid  = threadIdx.x;
    const int lane = tid & 31;
    const int warp = tid >> 5;
    const int wm   = warp >> 2;     // 0..1
    const int wn   = warp & 3;      // 0..3
    const int gid  = lane >> 2;     // 0..7
    const int tid4 = lane & 3;      // 0..3

    const int bn = blockIdx.x * GBN;
    const int bm = blockIdx.y * GBM;

    const float* __restrict__ A = QKV ? Ain : g_ctx;

    float d[4][4][4];
    #pragma unroll
    for (int i = 0; i < 4; i++)
        #pragma unroll
        for (int j = 0; j < 4; j++)
            #pragma unroll
            for (int r = 0; r < 4; r++) d[i][j][r] = 0.f;

    // ---- gmem load (thread t loads 4 float4 of A, 4 float4 of W) ----
    float4 aR[4], bR[4];

    auto ldg_chunk = [&](int c) {
        #pragma unroll
        for (int i = 0; i < 4; i++) {
            int j = tid + 256 * i;
            int m = j >> 3, kc4 = j & 7;
            aR[i] = *(const float4*)&A[(size_t)(bm + m) * KDIM + c * GBK + kc4 * 4];
        }
        #pragma unroll
        for (int i = 0; i < 4; i++) {
            int j = tid + 256 * i;
            int k = j >> 5, nc4 = j & 31;
            bR[i] = *(const float4*)&W[(size_t)(c * GBK + k) * ldn + bn + nc4 * 4];
        }
    };

    auto sts_chunk = [&](int buf) {
        float* Ab = As + buf * ABUF;
        float* Bb = Bs + buf * BBUF;
        #pragma unroll
        for (int i = 0; i < 4; i++) {
            int j = tid + 256 * i;
            int m = j >> 3, kc4 = j & 7;
            int tm = m >> 4, mr = m & 15;
            int g = mr & 7, hi = mr >> 3;
            int tk = kc4 >> 1, khi2 = (kc4 & 1) * 2;
            // in-tile idx = (g*4 + e4)*4 + hi + khi2  -> element stride 4
            int base = ((tk * 8 + tm) * 32 + g * 4) * 4 + hi + khi2;
            Ab[base + 0 * 4] = f2tf32(aR[i].x);
            Ab[base + 1 * 4] = f2tf32(aR[i].y);
            Ab[base + 2 * 4] = f2tf32(aR[i].z);
            Ab[base + 3 * 4] = f2tf32(aR[i].w);
        }
        #pragma unroll
        for (int i = 0; i < 4; i++) {
            int j = tid + 256 * i;
            int k = j >> 5, nc4 = j & 31;
            int tk = k >> 3, kr = k & 7;
            int regb = kr >> 2, k4 = kr & 3;
            int tn = nc4 >> 1, nhalf = (nc4 & 1) * 4;
            // in-tile idx = ((nhalf+e4)*4 + k4)*2 + regb -> element stride 8
            int base = ((tk * 16 + tn) * 32 + nhalf * 4 + k4) * 2 + regb;
            Bb[base + 0 * 8] = f2tf32(bR[i].x);
            Bb[base + 1 * 8] = f2tf32(bR[i].y);
            Bb[base + 2 * 8] = f2tf32(bR[i].z);
            Bb[base + 3 * 8] = f2tf32(bR[i].w);
        }
    };

    // prologue
    ldg_chunk(0);
    sts_chunk(0);

    for (int c = 0; c < NKIT; c++) {
        __syncthreads();
        const int buf = c & 1;
        if (c + 1 < NKIT) ldg_chunk(c + 1);

        const float* Ab = As + buf * ABUF;
        const float* Bb = Bs + buf * BBUF;
        #pragma unroll
        for (int tk = 0; tk < 4; tk++) {
            uint32_t af[4][4], bf[4][2];
            #pragma unroll
            for (int tm = 0; tm < 4; tm++) {
                float4 v = *(const float4*)&Ab[((tk * 8 + wm * 4 + tm) * 32 + lane) * 4];
                af[tm][0] = __float_as_uint(v.x);
                af[tm][1] = __float_as_uint(v.y);
                af[tm][2] = __float_as_uint(v.z);
                af[tm][3] = __float_as_uint(v.w);
            }
            #pragma unroll
            for (int tn = 0; tn < 4; tn++) {
                float2 v = *(const float2*)&Bb[((tk * 16 + wn * 4 + tn) * 32 + lane) * 2];
                bf[tn][0] = __float_as_uint(v.x);
                bf[tn][1] = __float_as_uint(v.y);
            }
            #pragma unroll
            for (int tm = 0; tm < 4; tm++)
                #pragma unroll
                for (int tn = 0; tn < 4; tn++)
                    mma_tf32(d[tm][tn], af[tm], bf[tn]);
        }

        if (c + 1 < NKIT) sts_chunk((c + 1) & 1);
    }

    // ---- epilogue ----
    const int bb  = bm >> 11;              // batch (block fully inside one)
    #pragma unroll
    for (int tm = 0; tm < 4; tm++) {
        int m0 = bm + wm * 64 + tm * 16 + gid;     // rows m0 and m0+8
        #pragma unroll
        for (int tn = 0; tn < 4; tn++) {
            int n0 = bn + wn * 32 + tn * 8 + tid4 * 2;
            float bx = __ldg(&bias[n0]);
            float by = __ldg(&bias[n0 + 1]);
            float v0 = d[tm][tn][0] + bx, v1 = d[tm][tn][1] + by;
            float v2 = d[tm][tn][2] + bx, v3 = d[tm][tn][3] + by;
            if (QKV) {
                int s = n0 >> 10, h = (n0 & 1023) >> 6, d0 = n0 & 63;
                int ll = m0 & (SEQ - 1);
                float* base = (s == 0 ? g_Q : (s == 1 ? g_K : g_V))
                              + ((size_t)(bb * NHEAD + h) * SEQ) * DHEAD + d0;
                *(float2*)(base + (size_t)ll * DHEAD)       = make_float2(v0, v1);
                *(float2*)(base + (size_t)(ll + 8) * DHEAD) = make_float2(v2, v3);
            } else {
                *(float2*)(out + (size_t)m0 * D_MODEL + n0)       = make_float2(v0, v1);
                *(float2*)(out + (size_t)(m0 + 8) * D_MODEL + n0) = make_float2(v2, v3);
            }
        }
    }
}

// ---------------------------------------------------------------------------
// Flash attention, fp32 (near FFMA roofline; tensorize next round).
// ---------------------------------------------------------------------------
#define KT 32

__global__ __launch_bounds__(128) void attn_kernel()
{
    __shared__ float Ks[KT * DHEAD];
    __shared__ float Vs[KT * DHEAD];
    __shared__ float Ss[128][KT + 1];

    const int tid = threadIdx.x;
    const int b  = blockIdx.z;
    const int h  = blockIdx.y;
    const int q0 = blockIdx.x * 128;

    const int head_off = ((b * NHEAD) + h) * SEQ * DHEAD;
    const float* __restrict__ Qb = g_Q + head_off;
    const float* __restrict__ Kb = g_K + head_off;
    const float* __restrict__ Vb = g_V + head_off;

    float q[DHEAD];
    {
        const float4* qr = (const float4*)(Qb + (q0 + tid) * DHEAD);
        #pragma unroll
        for (int i = 0; i < DHEAD / 4; i++) {
            float4 t = qr[i];
            q[4*i+0] = t.x; q[4*i+1] = t.y; q[4*i+2] = t.z; q[4*i+3] = t.w;
        }
    }

    float O[DHEAD];
    #pragma unroll
    for (int d = 0; d < DHEAD; d++) O[d] = 0.f;
    float m = -1e30f, l = 0.f;

    for (int kt = 0; kt < SEQ / KT; kt++) {
        const float4* ksrc = (const float4*)(Kb + kt * KT * DHEAD);
        const float4* vsrc = (const float4*)(Vb + kt * KT * DHEAD);
        #pragma unroll
        for (int i = 0; i < (KT * DHEAD / 4) / 128; i++) {
            ((float4*)Ks)[tid + i * 128] = ksrc[tid + i * 128];
            ((float4*)Vs)[tid + i * 128] = vsrc[tid + i * 128];
        }
        __syncthreads();

        for (int j = 0; j < KT; j++) {
            float a0 = 0.f, a1 = 0.f, a2 = 0.f, a3 = 0.f;
            #pragma unroll
            for (int d = 0; d < DHEAD; d += 4) {
                a0 += q[d + 0] * Ks[j * DHEAD + d + 0];
                a1 += q[d + 1] * Ks[j * DHEAD + d + 1];
                a2 += q[d + 2] * Ks[j * DHEAD + d + 2];
                a3 += q[d + 3] * Ks[j * DHEAD + d + 3];
            }
            Ss[tid][j] = (a0 + a1 + a2 + a3) * 0.125f;
        }

        float mt = m;
        for (int j = 0; j < KT; j++) mt = fmaxf(mt, Ss[tid][j]);
        float alpha = __expf(m - mt);
        m = mt;
        l *= alpha;
        #pragma unroll
        for (int d = 0; d < DHEAD; d++) O[d] *= alpha;

        for (int j = 0; j < KT; j++) {
            float p = __expf(Ss[tid][j] - m);
            l += p;
            #pragma unroll
            for (int d = 0; d < DHEAD; d++)
                O[d] += p * Vs[j * DHEAD + d];
        }
        __syncthreads();
    }

    float inv = 1.f / l;
    float* dst = g_ctx + (b * SEQ + q0 + tid) * D_MODEL + h * DHEAD;
    #pragma unroll
    for (int i = 0; i < DHEAD / 4; i++) {
        float4 t;
        t.x = O[4*i+0] * inv; t.y = O[4*i+1] * inv;
        t.z = O[4*i+2] * inv; t.w = O[4*i+3] * inv;
        ((float4*)dst)[i] = t;
    }
}

// ---------------------------------------------------------------------------

#define GEMM_SMEM (4 * 4096 * 4)   // 64 KB

extern "C" void kernel_launch(void* const* d_in, const int* in_sizes, int n_in,
                              void* d_out, int out_size)
{
    const float* x     = (const float*)d_in[0];
    const float* w_qkv = (const float*)d_in[1];
    const float* b_qkv = (const float*)d_in[2];
    const float* w_out = (const float*)d_in[3];
    const float* b_out = (const float*)d_in[4];
    float* out = (float*)d_out;

    (void)in_sizes; (void)n_in; (void)out_size;

    cudaFuncSetAttribute(tc_gemm<1>, cudaFuncAttributeMaxDynamicSharedMemorySize, GEMM_SMEM);
    cudaFuncSetAttribute(tc_gemm<0>, cudaFuncAttributeMaxDynamicSharedMemorySize, GEMM_SMEM);

    // 1) QKV projection (mma.sync tf32) + scatter into per-head layout
    tc_gemm<1><<<dim3(QKV_N / GBN, ROWS / GBM), 256, GEMM_SMEM>>>(
        x, w_qkv, b_qkv, nullptr, QKV_N);

    // 2) Attention (fp32)
    attn_kernel<<<dim3(SEQ / 128, NHEAD, BATCH), 128>>>();

    // 3) Output projection (mma.sync tf32)
    tc_gemm<0><<<dim3(D_MODEL / GBN, ROWS / GBM), 256, GEMM_SMEM>>>(
        nullptr, w_out, b_out, out, D_MODEL);
}

// round 11
// speedup vs baseline: 1.8419x; 1.8184x over previous
#include <cuda_runtime.h>
#include <cstdint>

#define D_MODEL 1024
#define NHEAD   16
#define DHEAD   64
#define BATCH   4
#define SEQ     2048
#define ROWS    (BATCH * SEQ)          // 8192
#define QKV_N   (3 * D_MODEL)          // 3072
#define KDIM    1024

// Scratch (allocation-free rule: __device__ globals)
__device__ float g_Q[BATCH * NHEAD * SEQ * DHEAD];   // [B,H,L,Dh]
__device__ float g_K[BATCH * NHEAD * SEQ * DHEAD];
__device__ float g_V[BATCH * NHEAD * SEQ * DHEAD];
__device__ float g_ctx[ROWS * D_MODEL];              // [B,L,H*Dh]

// ---------------------------------------------------------------------------
// helpers
// ---------------------------------------------------------------------------
__device__ __forceinline__ float f2tf32(float x) {
    uint32_t b;
    asm("cvt.rna.tf32.f32 %0, %1;" : "=r"(b) : "f"(x));
    return __uint_as_float(b);
}

// D += A*B, m16n8k8 tf32 (legacy tensor-core path, portable PTX)
__device__ __forceinline__ void mma_tf32(float* d, const uint32_t* a, const uint32_t* b) {
    asm volatile(
        "mma.sync.aligned.m16n8k8.row.col.f32.tf32.tf32.f32 "
        "{%0,%1,%2,%3}, {%4,%5,%6,%7}, {%8,%9}, {%0,%1,%2,%3};"
        : "+f"(d[0]), "+f"(d[1]), "+f"(d[2]), "+f"(d[3])
        : "r"(a[0]), "r"(a[1]), "r"(a[2]), "r"(a[3]), "r"(b[0]), "r"(b[1]));
}

__device__ __forceinline__ uint32_t smem_u32(const void* p) {
    uint32_t a;
    asm("{ .reg .u64 t; cvta.to.shared.u64 t, %1; cvt.u32.u64 %0, t; }"
        : "=r"(a) : "l"(p));
    return a;
}

__device__ __forceinline__ void cp16(uint32_t dst, const void* src) {
    asm volatile("cp.async.cg.shared.global [%0], [%1], 16;"
                 :: "r"(dst), "l"(src) : "memory");
}
#define CP_COMMIT() asm volatile("cp.async.commit_group;" ::: "memory")
#define CP_WAIT(n)  asm volatile("cp.async.wait_group %0;" :: "n"(n) : "memory")

// ---------------------------------------------------------------------------
// mma.sync tf32 GEMM (unchanged from R7): C[M,N] = A[M,1024] @ W[1024,N] + bias
// ---------------------------------------------------------------------------
#define GBM 128
#define GBN 128
#define GBK 32
#define NKIT (KDIM / GBK)        // 32
#define ABUF 4096
#define BBUF 4096

template<int QKV>
__global__ __launch_bounds__(256, 2) void tc_gemm(
    const float* __restrict__ Ain, const float* __restrict__ W,
    const float* __restrict__ bias, float* __restrict__ out, int ldn)
{
    extern __shared__ float sm[];
    float* As = sm;
    float* Bs = sm + 2 * ABUF;

    const int tid  = threadIdx.x;
    const int lane = tid & 31;
    const int warp = tid >> 5;
    const int wm   = warp >> 2;
    const int wn   = warp & 3;
    const int gid  = lane >> 2;
    const int tid4 = lane & 3;

    const int bn = blockIdx.x * GBN;
    const int bm = blockIdx.y * GBM;

    const float* __restrict__ A = QKV ? Ain : g_ctx;

    float d[4][4][4];
    #pragma unroll
    for (int i = 0; i < 4; i++)
        #pragma unroll
        for (int j = 0; j < 4; j++)
            #pragma unroll
            for (int r = 0; r < 4; r++) d[i][j][r] = 0.f;

    float4 aR[4], bR[4];

    auto ldg_chunk = [&](int c) {
        #pragma unroll
        for (int i = 0; i < 4; i++) {
            int j = tid + 256 * i;
            int m = j >> 3, kc4 = j & 7;
            aR[i] = *(const float4*)&A[(size_t)(bm + m) * KDIM + c * GBK + kc4 * 4];
        }
        #pragma unroll
        for (int i = 0; i < 4; i++) {
            int j = tid + 256 * i;
            int k = j >> 5, nc4 = j & 31;
            bR[i] = *(const float4*)&W[(size_t)(c * GBK + k) * ldn + bn + nc4 * 4];
        }
    };

    auto sts_chunk = [&](int buf) {
        float* Ab = As + buf * ABUF;
        float* Bb = Bs + buf * BBUF;
        #pragma unroll
        for (int i = 0; i < 4; i++) {
            int j = tid + 256 * i;
            int m = j >> 3, kc4 = j & 7;
            int tm = m >> 4, mr = m & 15;
            int g = mr & 7, hi = mr >> 3;
            int tk = kc4 >> 1, khi2 = (kc4 & 1) * 2;
            int base = ((tk * 8 + tm) * 32 + g * 4) * 4 + hi + khi2;
            Ab[base + 0 * 4] = f2tf32(aR[i].x);
            Ab[base + 1 * 4] = f2tf32(aR[i].y);
            Ab[base + 2 * 4] = f2tf32(aR[i].z);
            Ab[base + 3 * 4] = f2tf32(aR[i].w);
        }
        #pragma unroll
        for (int i = 0; i < 4; i++) {
            int j = tid + 256 * i;
            int k = j >> 5, nc4 = j & 31;
            int tk = k >> 3, kr = k & 7;
            int regb = kr >> 2, k4 = kr & 3;
            int tn = nc4 >> 1, nhalf = (nc4 & 1) * 4;
            int base = ((tk * 16 + tn) * 32 + nhalf * 4 + k4) * 2 + regb;
            Bb[base + 0 * 8] = f2tf32(bR[i].x);
            Bb[base + 1 * 8] = f2tf32(bR[i].y);
            Bb[base + 2 * 8] = f2tf32(bR[i].z);
            Bb[base + 3 * 8] = f2tf32(bR[i].w);
        }
    };

    ldg_chunk(0);
    sts_chunk(0);

    for (int c = 0; c < NKIT; c++) {
        __syncthreads();
        const int buf = c & 1;
        if (c + 1 < NKIT) ldg_chunk(c + 1);

        const float* Ab = As + buf * ABUF;
        const float* Bb = Bs + buf * BBUF;
        #pragma unroll
        for (int tk = 0; tk < 4; tk++) {
            uint32_t af[4][4], bf[4][2];
            #pragma unroll
            for (int tm = 0; tm < 4; tm++) {
                float4 v = *(const float4*)&Ab[((tk * 8 + wm * 4 + tm) * 32 + lane) * 4];
                af[tm][0] = __float_as_uint(v.x);
                af[tm][1] = __float_as_uint(v.y);
                af[tm][2] = __float_as_uint(v.z);
                af[tm][3] = __float_as_uint(v.w);
            }
            #pragma unroll
            for (int tn = 0; tn < 4; tn++) {
                float2 v = *(const float2*)&Bb[((tk * 16 + wn * 4 + tn) * 32 + lane) * 2];
                bf[tn][0] = __float_as_uint(v.x);
                bf[tn][1] = __float_as_uint(v.y);
            }
            #pragma unroll
            for (int tm = 0; tm < 4; tm++)
                #pragma unroll
                for (int tn = 0; tn < 4; tn++)
                    mma_tf32(d[tm][tn], af[tm], bf[tn]);
        }

        if (c + 1 < NKIT) sts_chunk((c + 1) & 1);
    }

    const int bb = bm >> 11;
    #pragma unroll
    for (int tm = 0; tm < 4; tm++) {
        int m0 = bm + wm * 64 + tm * 16 + gid;
        #pragma unroll
        for (int tn = 0; tn < 4; tn++) {
            int n0 = bn + wn * 32 + tn * 8 + tid4 * 2;
            float bx = __ldg(&bias[n0]);
            float by = __ldg(&bias[n0 + 1]);
            float v0 = d[tm][tn][0] + bx, v1 = d[tm][tn][1] + by;
            float v2 = d[tm][tn][2] + bx, v3 = d[tm][tn][3] + by;
            if (QKV) {
                int s = n0 >> 10, h = (n0 & 1023) >> 6, d0 = n0 & 63;
                int ll = m0 & (SEQ - 1);
                float* base = (s == 0 ? g_Q : (s == 1 ? g_K : g_V))
                              + ((size_t)(bb * NHEAD + h) * SEQ) * DHEAD + d0;
                *(float2*)(base + (size_t)ll * DHEAD)       = make_float2(v0, v1);
                *(float2*)(base + (size_t)(ll + 8) * DHEAD) = make_float2(v2, v3);
            } else {
                *(float2*)(out + (size_t)m0 * D_MODEL + n0)       = make_float2(v0, v1);
                *(float2*)(out + (size_t)(m0 + 8) * D_MODEL + n0) = make_float2(v2, v3);
            }
        }
    }
}

// ---------------------------------------------------------------------------
// Tensor-core flash attention (mma.sync tf32).
// CTA: 64 q rows, 4 warps (warp = 16 q rows). Key tiles of 64.
// K staged row-major stride 68 (bank = (4g+t4)&31, conflict-free).
// V staged row-major stride 72 (bank = (8t4+g)&31, conflict-free).
// Double-buffered cp.async.cg. Softmax + P-layout conversion in registers.
// Fragment maps (g = lane>>2, t4 = lane&3):
//   A: a0=(g,t4) a1=(g+8,t4) a2=(g,t4+4) a3=(g+8,t4+4)
//   B: b0=(k=t4,n=g) b1=(k=t4+4,n=g)
//   D: d0=(g,2t4) d1=(g,2t4+1) d2=(g+8,2t4) d3=(g+8,2t4+1)
// ---------------------------------------------------------------------------
#define ATT_KT   64
#define K_STRIDE 68
#define V_STRIDE 72
#define KB_BYTES (64 * K_STRIDE * 4)   // 17408
#define VB_BYTES (64 * V_STRIDE * 4)   // 18432
#define ATT_SMEM (2 * (KB_BYTES + VB_BYTES))  // 71680

__global__ __launch_bounds__(128) void attn_mma_kernel()
{
    extern __shared__ float asm_[];

    const int tid  = threadIdx.x;
    const int lane = tid & 31;
    const int wid  = tid >> 5;
    const int g    = lane >> 2;
    const int t4   = lane & 3;

    const int b  = blockIdx.z;
    const int h  = blockIdx.y;
    const int q0 = blockIdx.x * 64;

    const size_t head_off = ((size_t)(b * NHEAD) + h) * SEQ * DHEAD;
    const float* __restrict__ Qb = g_Q + head_off;
    const float* __restrict__ Kb = g_K + head_off;
    const float* __restrict__ Vb = g_V + head_off;

    const uint32_t smb = smem_u32(asm_);

    // ---- load Q fragments (rna tf32, scale folded) ----
    uint32_t qa[8][4];
    {
        const float* Qr = Qb + (size_t)(q0 + wid * 16) * DHEAD;
        #pragma unroll
        for (int c = 0; c < 8; c++) {
            qa[c][0] = __float_as_uint(f2tf32(0.125f * __ldg(&Qr[(size_t)g * 64 + 8 * c + t4])));
            qa[c][1] = __float_as_uint(f2tf32(0.125f * __ldg(&Qr[(size_t)(g + 8) * 64 + 8 * c + t4])));
            qa[c][2] = __float_as_uint(f2tf32(0.125f * __ldg(&Qr[(size_t)g * 64 + 8 * c + t4 + 4])));
            qa[c][3] = __float_as_uint(f2tf32(0.125f * __ldg(&Qr[(size_t)(g + 8) * 64 + 8 * c + t4 + 4])));
        }
    }

    float o[8][4];
    #pragma unroll
    for (int j = 0; j < 8; j++)
        #pragma unroll
        for (int r = 0; r < 4; r++) o[j][r] = 0.f;
    float m0 = -1e30f, m1 = -1e30f, l0 = 0.f, l1 = 0.f;

    // ---- staging ----
    auto stage = [&](int kt, int buf) {
        uint32_t kd = smb + buf * (KB_BYTES + VB_BYTES);
        uint32_t vd = kd + KB_BYTES;
        #pragma unroll
        for (int i = 0; i < 8; i++) {
            int j = tid + 128 * i;
            int row = j >> 4, c4 = j & 15;
            cp16(kd + (uint32_t)(row * K_STRIDE + c4 * 4) * 4,
                 Kb + (size_t)(kt * ATT_KT + row) * DHEAD + c4 * 4);
            cp16(vd + (uint32_t)(row * V_STRIDE + c4 * 4) * 4,
                 Vb + (size_t)(kt * ATT_KT + row) * DHEAD + c4 * 4);
        }
    };

    stage(0, 0);
    CP_COMMIT();

    const int NT = SEQ / ATT_KT;   // 32
    for (int kt = 0; kt < NT; kt++) {
        if (kt + 1 < NT) {
            stage(kt + 1, (kt + 1) & 1);
            CP_COMMIT();
            CP_WAIT(1);
        } else {
            CP_WAIT(0);
        }
        __syncthreads();

        const float* Ksp = asm_ + (kt & 1) * (KB_BYTES + VB_BYTES) / 4;
        const float* Vsp = Ksp + KB_BYTES / 4;

        // ---- S = Q @ K^T ----
        float sj[8][4];
        #pragma unroll
        for (int j = 0; j < 8; j++) {
            sj[j][0] = sj[j][1] = sj[j][2] = sj[j][3] = 0.f;
            #pragma unroll
            for (int c = 0; c < 8; c++) {
                uint32_t bf[2];
                const float* kr = Ksp + (8 * j + g) * K_STRIDE + 8 * c + t4;
                bf[0] = __float_as_uint(kr[0]);
                bf[1] = __float_as_uint(kr[4]);
                mma_tf32(sj[j], qa[c], bf);
            }
        }

        // ---- online softmax (registers + t4-quad butterflies) ----
        float mt0 = -1e30f, mt1 = -1e30f;
        #pragma unroll
        for (int j = 0; j < 8; j++) {
            mt0 = fmaxf(mt0, fmaxf(sj[j][0], sj[j][1]));
            mt1 = fmaxf(mt1, fmaxf(sj[j][2], sj[j][3]));
        }
        mt0 = fmaxf(mt0, __shfl_xor_sync(0xffffffffu, mt0, 1));
        mt0 = fmaxf(mt0, __shfl_xor_sync(0xffffffffu, mt0, 2));
        mt1 = fmaxf(mt1, __shfl_xor_sync(0xffffffffu, mt1, 1));
        mt1 = fmaxf(mt1, __shfl_xor_sync(0xffffffffu, mt1, 2));

        float mn0 = fmaxf(m0, mt0), mn1 = fmaxf(m1, mt1);
        float a0 = __expf(m0 - mn0), a1 = __expf(m1 - mn1);
        m0 = mn0; m1 = mn1;

        float rs0 = 0.f, rs1 = 0.f;
        #pragma unroll
        for (int j = 0; j < 8; j++) {
            sj[j][0] = __expf(sj[j][0] - mn0);
            sj[j][1] = __expf(sj[j][1] - mn0);
            sj[j][2] = __expf(sj[j][2] - mn1);
            sj[j][3] = __expf(sj[j][3] - mn1);
            rs0 += sj[j][0] + sj[j][1];
            rs1 += sj[j][2] + sj[j][3];
        }
        rs0 += __shfl_xor_sync(0xffffffffu, rs0, 1);
        rs0 += __shfl_xor_sync(0xffffffffu, rs0, 2);
        rs1 += __shfl_xor_sync(0xffffffffu, rs1, 1);
        rs1 += __shfl_xor_sync(0xffffffffu, rs1, 2);
        l0 = l0 * a0 + rs0;
        l1 = l1 * a1 + rs1;

        #pragma unroll
        for (int j = 0; j < 8; j++) {
            o[j][0] *= a0; o[j][1] *= a0;
            o[j][2] *= a1; o[j][3] *= a1;
        }

        // ---- P: D-layout -> A-layout (shuffles) ----
        uint32_t pa[8][4];
        const int srcA = (lane & 28) | (t4 >> 1);
        const int srcB = srcA + 2;
        const bool odd = t4 & 1;
        #pragma unroll
        for (int j = 0; j < 8; j++) {
            float s0 = __shfl_sync(0xffffffffu, sj[j][0], srcA);
            float s1 = __shfl_sync(0xffffffffu, sj[j][1], srcA);
            float s2 = __shfl_sync(0xffffffffu, sj[j][0], srcB);
            float s3 = __shfl_sync(0xffffffffu, sj[j][1], srcB);
            float u0 = __shfl_sync(0xffffffffu, sj[j][2], srcA);
            float u1 = __shfl_sync(0xffffffffu, sj[j][3], srcA);
            float u2 = __shfl_sync(0xffffffffu, sj[j][2], srcB);
            float u3 = __shfl_sync(0xffffffffu, sj[j][3], srcB);
            pa[j][0] = __float_as_uint(odd ? s1 : s0);
            pa[j][1] = __float_as_uint(odd ? u1 : u0);
            pa[j][2] = __float_as_uint(odd ? s3 : s2);
            pa[j][3] = __float_as_uint(odd ? u3 : u2);
        }

        // ---- O += P @ V ----
        #pragma unroll
        for (int j = 0; j < 8; j++) {
            #pragma unroll
            for (int c = 0; c < 8; c++) {
                uint32_t bf[2];
                const float* vr = Vsp + (8 * c + t4) * V_STRIDE + 8 * j + g;
                bf[0] = __float_as_uint(vr[0]);
                bf[1] = __float_as_uint(vr[4 * V_STRIDE]);
                mma_tf32(o[j], pa[c], bf);
            }
        }

        __syncthreads();
    }

    // ---- epilogue: O / l -> g_ctx [B, L, H*Dh] ----
    float inv0 = 1.f / l0, inv1 = 1.f / l1;
    size_t row0 = (size_t)(b * SEQ + q0 + wid * 16 + g);
    float* dst0 = g_ctx + row0 * D_MODEL + h * DHEAD;
    float* dst1 = dst0 + 8 * D_MODEL;
    #pragma unroll
    for (int j = 0; j < 8; j++) {
        *(float2*)(dst0 + 8 * j + 2 * t4) = make_float2(o[j][0] * inv0, o[j][1] * inv0);
        *(float2*)(dst1 + 8 * j + 2 * t4) = make_float2(o[j][2] * inv1, o[j][3] * inv1);
    }
}

// ---------------------------------------------------------------------------

#define GEMM_SMEM (4 * 4096 * 4)   // 64 KB

extern "C" void kernel_launch(void* const* d_in, const int* in_sizes, int n_in,
                              void* d_out, int out_size)
{
    const float* x     = (const float*)d_in[0];
    const float* w_qkv = (const float*)d_in[1];
    const float* b_qkv = (const float*)d_in[2];
    const float* w_out = (const float*)d_in[3];
    const float* b_out = (const float*)d_in[4];
    float* out = (float*)d_out;

    (void)in_sizes; (void)n_in; (void)out_size;

    cudaFuncSetAttribute(tc_gemm<1>, cudaFuncAttributeMaxDynamicSharedMemorySize, GEMM_SMEM);
    cudaFuncSetAttribute(tc_gemm<0>, cudaFuncAttributeMaxDynamicSharedMemorySize, GEMM_SMEM);
    cudaFuncSetAttribute(attn_mma_kernel, cudaFuncAttributeMaxDynamicSharedMemorySize, ATT_SMEM);

    // 1) QKV projection (mma.sync tf32) + scatter into per-head layout
    tc_gemm<1><<<dim3(QKV_N / GBN, ROWS / GBM), 256, GEMM_SMEM>>>(
        x, w_qkv, b_qkv, nullptr, QKV_N);

    // 2) Attention (mma.sync tf32 flash)
    attn_mma_kernel<<<dim3(SEQ / 64, NHEAD, BATCH), 128, ATT_SMEM>>>();

    // 3) Output projection (mma.sync tf32)
    tc_gemm<0><<<dim3(D_MODEL / GBN, ROWS / GBM), 256, GEMM_SMEM>>>(
        nullptr, w_out, b_out, out, D_MODEL);
}

// round 14
// speedup vs baseline: 3.9560x; 2.1477x over previous
#include <cuda_runtime.h>
#include <cstdint>

#define D_MODEL 1024
#define NHEAD   16
#define DHEAD   64
#define BATCH   4
#define SEQ     2048
#define ROWS    (BATCH * SEQ)          // 8192
#define QKV_N   (3 * D_MODEL)          // 3072
#define KDIM    1024

// Scratch (allocation-free rule: __device__ globals)
__device__ float g_Q[BATCH * NHEAD * SEQ * DHEAD];   // [B,H,L,Dh]
__device__ float g_K[BATCH * NHEAD * SEQ * DHEAD];
__device__ float g_V[BATCH * NHEAD * SEQ * DHEAD];
__device__ float g_ctx[ROWS * D_MODEL];              // [B,L,H*Dh] (tf32-rounded)
__device__ float g_Xt[ROWS * KDIM];                  // x, tf32(rna)
__device__ float g_Wq[KDIM * QKV_N];                 // w_qkv, tf32(rna)
__device__ float g_Wo[KDIM * D_MODEL];               // w_out, tf32(rna)

// ---------------------------------------------------------------------------
// helpers
// ---------------------------------------------------------------------------
__device__ __forceinline__ float f2tf32(float x) {
    uint32_t b;
    asm("cvt.rna.tf32.f32 %0, %1;" : "=r"(b) : "f"(x));
    return __uint_as_float(b);
}

// D += A*B, m16n8k8 tf32 (legacy tensor-core path, portable PTX)
__device__ __forceinline__ void mma_tf32(float* d, const uint32_t* a, const uint32_t* b) {
    asm volatile(
        "mma.sync.aligned.m16n8k8.row.col.f32.tf32.tf32.f32 "
        "{%0,%1,%2,%3}, {%4,%5,%6,%7}, {%8,%9}, {%0,%1,%2,%3};"
        : "+f"(d[0]), "+f"(d[1]), "+f"(d[2]), "+f"(d[3])
        : "r"(a[0]), "r"(a[1]), "r"(a[2]), "r"(a[3]), "r"(b[0]), "r"(b[1]));
}

__device__ __forceinline__ uint32_t smem_u32(const void* p) {
    uint32_t a;
    asm("{ .reg .u64 t; cvta.to.shared.u64 t, %1; cvt.u32.u64 %0, t; }"
        : "=r"(a) : "l"(p));
    return a;
}

__device__ __forceinline__ void cp16(uint32_t dst, const void* src) {
    asm volatile("cp.async.cg.shared.global [%0], [%1], 16;"
                 :: "r"(dst), "l"(src) : "memory");
}
#define CP_COMMIT() asm volatile("cp.async.commit_group;" ::: "memory")
#define CP_WAIT(n)  asm volatile("cp.async.wait_group %0;" :: "n"(n) : "memory")

// ---------------------------------------------------------------------------
// tf32(rna) pre-conversion
// ---------------------------------------------------------------------------
__global__ __launch_bounds__(256) void conv_tf32(
    const float* __restrict__ src, float* __restrict__ dst)
{
    int i = blockIdx.x * 256 + threadIdx.x;
    float4 v = ((const float4*)src)[i];
    v.x = f2tf32(v.x); v.y = f2tf32(v.y);
    v.z = f2tf32(v.z); v.w = f2tf32(v.w);
    ((float4*)dst)[i] = v;
}

// ---------------------------------------------------------------------------
// mma.sync tf32 GEMM: C[M,N] = A[M,1024] @ W[1024,N] + bias
// Inputs pre-rounded to tf32. cp.async 3-stage pipeline.
// CTA tile 128x128, BK=32, 256 threads = 8 warps (2m x 4n), warp tile 64x32.
//
// A stage [128][32] floats, float4-group XOR swizzle:
//   off(row, kc4) = row*32 + ((kc4 ^ (row&7)) << 2)        (+ k&3)
//   cp.async: warp writes 512B contiguous (perm within rows) - conflict-free.
//   frag LDS bank = ((2tk ^ g)*4 + t4) & 31 -> 32 distinct  - conflict-free.
// B stage [32][136] floats (8-float row pad):
//   off(k, n) = k*136 + n
//   cp.async: warp writes 512B contiguous in one row        - conflict-free.
//   frag LDS bank = (8*t4 + g + n0) & 31 -> 32 distinct     - conflict-free.
// ---------------------------------------------------------------------------
#define GBM 128
#define GBN 128
#define GBK 32
#define NKIT (KDIM / GBK)        // 32
#define ASTG 4096                // floats: 128*32
#define BSTG 4352                // floats: 32*136
#define STG  (ASTG + BSTG)       // 8448 floats = 33792 B
#define NSTAGE 3
#define GEMM_SMEM (NSTAGE * STG * 4)   // 101376 B

template<int QKV>
__global__ __launch_bounds__(256) void tc_gemm(
    const float* __restrict__ A, const float* __restrict__ W,
    const float* __restrict__ bias, float* __restrict__ out, int ldn)
{
    extern __shared__ float sm[];

    const int tid  = threadIdx.x;
    const int lane = tid & 31;
    const int warp = tid >> 5;
    const int wm   = warp >> 2;     // 0..1
    const int wn   = warp & 3;      // 0..3
    const int g    = lane >> 2;     // 0..7
    const int t4   = lane & 3;      // 0..3

    const int bn = blockIdx.x * GBN;
    const int bm = blockIdx.y * GBM;

    float d[4][4][4];
    #pragma unroll
    for (int i = 0; i < 4; i++)
        #pragma unroll
        for (int j = 0; j < 4; j++)
            #pragma unroll
            for (int r = 0; r < 4; r++) d[i][j][r] = 0.f;

    const uint32_t smb = smem_u32(sm);

    auto stage = [&](int c, int buf) {
        uint32_t ab = smb + (uint32_t)buf * (STG * 4);
        uint32_t bb = ab + ASTG * 4;
        #pragma unroll
        for (int i = 0; i < 4; i++) {
            int j = tid + 256 * i;
            int m = j >> 3, kc4 = j & 7;
            cp16(ab + (uint32_t)(m * 32 + ((kc4 ^ (m & 7)) << 2)) * 4,
                 A + (size_t)(bm + m) * KDIM + c * GBK + kc4 * 4);
        }
        #pragma unroll
        for (int i = 0; i < 4; i++) {
            int j = tid + 256 * i;
            int k = j >> 5, nc4 = j & 31;
            cp16(bb + (uint32_t)(k * 136 + nc4 * 4) * 4,
                 W + (size_t)(c * GBK + k) * ldn + bn + nc4 * 4);
        }
    };

    stage(0, 0); CP_COMMIT();
    stage(1, 1); CP_COMMIT();

    int buf = 0;
    for (int c = 0; c < NKIT; c++) {
        CP_WAIT(1);
        __syncthreads();

        const float* Ab = sm + buf * STG;
        const float* Bb = Ab + ASTG;

        #pragma unroll
        for (int tk = 0; tk < 4; tk++) {
            uint32_t af[4][4], bf[4][2];
            #pragma unroll
            for (int tm = 0; tm < 4; tm++) {
                int row = wm * 64 + tm * 16 + g;       // row&7 == g
                int s0 = ((2 * tk) ^ g) << 2;
                int s1 = ((2 * tk + 1) ^ g) << 2;
                af[tm][0] = __float_as_uint(Ab[row * 32 + s0 + t4]);
                af[tm][1] = __float_as_uint(Ab[(row + 8) * 32 + s0 + t4]);
                af[tm][2] = __float_as_uint(Ab[row * 32 + s1 + t4]);
                af[tm][3] = __float_as_uint(Ab[(row + 8) * 32 + s1 + t4]);
            }
            #pragma unroll
            for (int tn = 0; tn < 4; tn++) {
                int n = wn * 32 + tn * 8 + g;
                bf[tn][0] = __float_as_uint(Bb[(8 * tk + t4) * 136 + n]);
                bf[tn][1] = __float_as_uint(Bb[(8 * tk + t4 + 4) * 136 + n]);
            }
            #pragma unroll
            for (int tm = 0; tm < 4; tm++)
                #pragma unroll
                for (int tn = 0; tn < 4; tn++)
                    mma_tf32(d[tm][tn], af[tm], bf[tn]);
        }

        __syncthreads();
        if (c + 2 < NKIT) stage(c + 2, (buf + 2) % NSTAGE);
        CP_COMMIT();

        buf = (buf + 1) % NSTAGE;
    }

    // ---- epilogue ----
    const int bb2 = bm >> 11;              // batch (block fully inside one)
    #pragma unroll
    for (int tm = 0; tm < 4; tm++) {
        int m0 = bm + wm * 64 + tm * 16 + g;
        #pragma unroll
        for (int tn = 0; tn < 4; tn++) {
            int n0 = bn + wn * 32 + tn * 8 + t4 * 2;
            float bx = __ldg(&bias[n0]);
            float by = __ldg(&bias[n0 + 1]);
            float v0 = d[tm][tn][0] + bx, v1 = d[tm][tn][1] + by;
            float v2 = d[tm][tn][2] + bx, v3 = d[tm][tn][3] + by;
            if (QKV) {
                int s = n0 >> 10, h = (n0 & 1023) >> 6, d0 = n0 & 63;
                int ll = m0 & (SEQ - 1);
                float* base = (s == 0 ? g_Q : (s == 1 ? g_K : g_V))
                              + ((size_t)(bb2 * NHEAD + h) * SEQ) * DHEAD + d0;
                *(float2*)(base + (size_t)ll * DHEAD)       = make_float2(v0, v1);
                *(float2*)(base + (size_t)(ll + 8) * DHEAD) = make_float2(v2, v3);
            } else {
                *(float2*)(out + (size_t)m0 * D_MODEL + n0)       = make_float2(v0, v1);
                *(float2*)(out + (size_t)(m0 + 8) * D_MODEL + n0) = make_float2(v2, v3);
            }
        }
    }
}

// ---------------------------------------------------------------------------
// Tensor-core flash attention (mma.sync tf32).
// ---------------------------------------------------------------------------
#define ATT_KT   64
#define K_STRIDE 68
#define V_STRIDE 72
#define KB_BYTES (64 * K_STRIDE * 4)   // 17408
#define VB_BYTES (64 * V_STRIDE * 4)   // 18432
#define ATT_SMEM (2 * (KB_BYTES + VB_BYTES))  // 71680

__global__ __launch_bounds__(128) void attn_mma_kernel()
{
    extern __shared__ float asm_[];

    const int tid  = threadIdx.x;
    const int lane = tid & 31;
    const int wid  = tid >> 5;
    const int g    = lane >> 2;
    const int t4   = lane & 3;

    const int b  = blockIdx.z;
    const int h  = blockIdx.y;
    const int q0 = blockIdx.x * 64;

    const size_t head_off = ((size_t)(b * NHEAD) + h) * SEQ * DHEAD;
    const float* __restrict__ Qb = g_Q + head_off;
    const float* __restrict__ Kb = g_K + head_off;
    const float* __restrict__ Vb = g_V + head_off;

    const uint32_t smb = smem_u32(asm_);

    // ---- load Q fragments (rna tf32, scale folded) ----
    uint32_t qa[8][4];
    {
        const float* Qr = Qb + (size_t)(q0 + wid * 16) * DHEAD;
        #pragma unroll
        for (int c = 0; c < 8; c++) {
            qa[c][0] = __float_as_uint(f2tf32(0.125f * __ldg(&Qr[(size_t)g * 64 + 8 * c + t4])));
            qa[c][1] = __float_as_uint(f2tf32(0.125f * __ldg(&Qr[(size_t)(g + 8) * 64 + 8 * c + t4])));
            qa[c][2] = __float_as_uint(f2tf32(0.125f * __ldg(&Qr[(size_t)g * 64 + 8 * c + t4 + 4])));
            qa[c][3] = __float_as_uint(f2tf32(0.125f * __ldg(&Qr[(size_t)(g + 8) * 64 + 8 * c + t4 + 4])));
        }
    }

    float o[8][4];
    #pragma unroll
    for (int j = 0; j < 8; j++)
        #pragma unroll
        for (int r = 0; r < 4; r++) o[j][r] = 0.f;
    float m0 = -1e30f, m1 = -1e30f, l0 = 0.f, l1 = 0.f;

    auto stage = [&](int kt, int buf) {
        uint32_t kd = smb + buf * (KB_BYTES + VB_BYTES);
        uint32_t vd = kd + KB_BYTES;
        #pragma unroll
        for (int i = 0; i < 8; i++) {
            int j = tid + 128 * i;
            int row = j >> 4, c4 = j & 15;
            cp16(kd + (uint32_t)(row * K_STRIDE + c4 * 4) * 4,
                 Kb + (size_t)(kt * ATT_KT + row) * DHEAD + c4 * 4);
            cp16(vd + (uint32_t)(row * V_STRIDE + c4 * 4) * 4,
                 Vb + (size_t)(kt * ATT_KT + row) * DHEAD + c4 * 4);
        }
    };

    stage(0, 0);
    CP_COMMIT();

    const int NT = SEQ / ATT_KT;   // 32
    for (int kt = 0; kt < NT; kt++) {
        if (kt + 1 < NT) {
            stage(kt + 1, (kt + 1) & 1);
            CP_COMMIT();
            CP_WAIT(1);
        } else {
            CP_WAIT(0);
        }
        __syncthreads();

        const float* Ksp = asm_ + (kt & 1) * (KB_BYTES + VB_BYTES) / 4;
        const float* Vsp = Ksp + KB_BYTES / 4;

        // ---- S = Q @ K^T ----
        float sj[8][4];
        #pragma unroll
        for (int j = 0; j < 8; j++) {
            sj[j][0] = sj[j][1] = sj[j][2] = sj[j][3] = 0.f;
            #pragma unroll
            for (int c = 0; c < 8; c++) {
                uint32_t bf[2];
                const float* kr = Ksp + (8 * j + g) * K_STRIDE + 8 * c + t4;
                bf[0] = __float_as_uint(kr[0]);
                bf[1] = __float_as_uint(kr[4]);
                mma_tf32(sj[j], qa[c], bf);
            }
        }

        // ---- online softmax ----
        float mt0 = -1e30f, mt1 = -1e30f;
        #pragma unroll
        for (int j = 0; j < 8; j++) {
            mt0 = fmaxf(mt0, fmaxf(sj[j][0], sj[j][1]));
            mt1 = fmaxf(mt1, fmaxf(sj[j][2], sj[j][3]));
        }
        mt0 = fmaxf(mt0, __shfl_xor_sync(0xffffffffu, mt0, 1));
        mt0 = fmaxf(mt0, __shfl_xor_sync(0xffffffffu, mt0, 2));
        mt1 = fmaxf(mt1, __shfl_xor_sync(0xffffffffu, mt1, 1));
        mt1 = fmaxf(mt1, __shfl_xor_sync(0xffffffffu, mt1, 2));

        float mn0 = fmaxf(m0, mt0), mn1 = fmaxf(m1, mt1);
        float a0 = __expf(m0 - mn0), a1 = __expf(m1 - mn1);
        m0 = mn0; m1 = mn1;

        float rs0 = 0.f, rs1 = 0.f;
        #pragma unroll
        for (int j = 0; j < 8; j++) {
            sj[j][0] = __expf(sj[j][0] - mn0);
            sj[j][1] = __expf(sj[j][1] - mn0);
            sj[j][2] = __expf(sj[j][2] - mn1);
            sj[j][3] = __expf(sj[j][3] - mn1);
            rs0 += sj[j][0] + sj[j][1];
            rs1 += sj[j][2] + sj[j][3];
        }
        rs0 += __shfl_xor_sync(0xffffffffu, rs0, 1);
        rs0 += __shfl_xor_sync(0xffffffffu, rs0, 2);
        rs1 += __shfl_xor_sync(0xffffffffu, rs1, 1);
        rs1 += __shfl_xor_sync(0xffffffffu, rs1, 2);
        l0 = l0 * a0 + rs0;
        l1 = l1 * a1 + rs1;

        #pragma unroll
        for (int j = 0; j < 8; j++) {
            o[j][0] *= a0; o[j][1] *= a0;
            o[j][2] *= a1; o[j][3] *= a1;
        }

        // ---- P: D-layout -> A-layout (shuffles) ----
        uint32_t pa[8][4];
        const int srcA = (lane & 28) | (t4 >> 1);
        const int srcB = srcA + 2;
        const bool odd = t4 & 1;
        #pragma unroll
        for (int j = 0; j < 8; j++) {
            float s0 = __shfl_sync(0xffffffffu, sj[j][0], srcA);
            float s1 = __shfl_sync(0xffffffffu, sj[j][1], srcA);
            float s2 = __shfl_sync(0xffffffffu, sj[j][0], srcB);
            float s3 = __shfl_sync(0xffffffffu, sj[j][1], srcB);
            float u0 = __shfl_sync(0xffffffffu, sj[j][2], srcA);
            float u1 = __shfl_sync(0xffffffffu, sj[j][3], srcA);
            float u2 = __shfl_sync(0xffffffffu, sj[j][2], srcB);
            float u3 = __shfl_sync(0xffffffffu, sj[j][3], srcB);
            pa[j][0] = __float_as_uint(odd ? s1 : s0);
            pa[j][1] = __float_as_uint(odd ? u1 : u0);
            pa[j][2] = __float_as_uint(odd ? s3 : s2);
            pa[j][3] = __float_as_uint(odd ? u3 : u2);
        }

        // ---- O += P @ V ----
        #pragma unroll
        for (int j = 0; j < 8; j++) {
            #pragma unroll
            for (int c = 0; c < 8; c++) {
                uint32_t bf[2];
                const float* vr = Vsp + (8 * c + t4) * V_STRIDE + 8 * j + g;
                bf[0] = __float_as_uint(vr[0]);
                bf[1] = __float_as_uint(vr[4 * V_STRIDE]);
                mma_tf32(o[j], pa[c], bf);
            }
        }

        __syncthreads();
    }

    // ---- epilogue: tf32-rounded ctx (feeds cp.async out-projection) ----
    float inv0 = 1.f / l0, inv1 = 1.f / l1;
    size_t row0 = (size_t)(b * SEQ + q0 + wid * 16 + g);
    float* dst0 = g_ctx + row0 * D_MODEL + h * DHEAD;
    float* dst1 = dst0 + 8 * D_MODEL;
    #pragma unroll
    for (int j = 0; j < 8; j++) {
        *(float2*)(dst0 + 8 * j + 2 * t4) =
            make_float2(f2tf32(o[j][0] * inv0), f2tf32(o[j][1] * inv0));
        *(float2*)(dst1 + 8 * j + 2 * t4) =
            make_float2(f2tf32(o[j][2] * inv1), f2tf32(o[j][3] * inv1));
    }
}

// ---------------------------------------------------------------------------

extern "C" void kernel_launch(void* const* d_in, const int* in_sizes, int n_in,
                              void* d_out, int out_size)
{
    const float* x     = (const float*)d_in[0];
    const float* w_qkv = (const float*)d_in[1];
    const float* b_qkv = (const float*)d_in[2];
    const float* w_out = (const float*)d_in[3];
    const float* b_out = (const float*)d_in[4];
    float* out = (float*)d_out;

    (void)in_sizes; (void)n_in; (void)out_size;

    cudaFuncSetAttribute(tc_gemm<1>, cudaFuncAttributeMaxDynamicSharedMemorySize, GEMM_SMEM);
    cudaFuncSetAttribute(tc_gemm<0>, cudaFuncAttributeMaxDynamicSharedMemorySize, GEMM_SMEM);
    cudaFuncSetAttribute(attn_mma_kernel, cudaFuncAttributeMaxDynamicSharedMemorySize, ATT_SMEM);

    float* gXt;  cudaGetSymbolAddress((void**)&gXt,  g_Xt);
    float* gWq;  cudaGetSymbolAddress((void**)&gWq,  g_Wq);
    float* gWo;  cudaGetSymbolAddress((void**)&gWo,  g_Wo);
    float* gCtx; cudaGetSymbolAddress((void**)&gCtx, g_ctx);   // R12 bug: was passing host shadow

    // 0) one-shot tf32(rna) pre-rounding of GEMM inputs
    conv_tf32<<<(ROWS * KDIM / 4) / 256, 256>>>(x, gXt);
    conv_tf32<<<(KDIM * QKV_N / 4) / 256, 256>>>(w_qkv, gWq);
    conv_tf32<<<(KDIM * D_MODEL / 4) / 256, 256>>>(w_out, gWo);

    // 1) QKV projection (mma.sync tf32, cp.async feed) + per-head scatter
    tc_gemm<1><<<dim3(QKV_N / GBN, ROWS / GBM), 256, GEMM_SMEM>>>(
        gXt, gWq, b_qkv, nullptr, QKV_N);

    // 2) Attention (mma.sync tf32 flash)
    attn_mma_kernel<<<dim3(SEQ / 64, NHEAD, BATCH), 128, ATT_SMEM>>>();

    // 3) Output projection (mma.sync tf32, cp.async feed)
    tc_gemm<0><<<dim3(D_MODEL / GBN, ROWS / GBM), 256, GEMM_SMEM>>>(
        gCtx, gWo, b_out, out, D_MODEL);
}